// round 6
// baseline (speedup 1.0000x reference)
#include <cuda_runtime.h>
#include <cuda_bf16.h>
#include <math.h>

#define NN   50000
#define NE   800000
#define NE2  850000   // NE + NN self loops
#define HC   128

// ---------------- scratch (device globals; float4 => guaranteed 16B align) --
__device__ float  g_wsum[NN];
__device__ float  g_deg[NN];
__device__ float  g_loopw[NN];
__device__ float4 g_xl[NN * 32];
__device__ float4 g_xr[NN * 32];
__device__ float4 g_ex[NE2];          // 4 heads per edge
__device__ float4 g_denom[NN];        // 4 heads per node
__device__ float4 g_agg[NN * 32];
__device__ float4 g_h1[NN * 32];
__device__ float  g_bnsum[HC];
__device__ float  g_bnsq[HC];
__device__ float4 g_bnscale[32];
__device__ float4 g_bnshift[32];

// ---------------- init / small kernels --------------------------------------
__global__ void __launch_bounds__(256) k_zero_pre() {
    int i = blockIdx.x * 256 + threadIdx.x;
    if (i < NN) { g_wsum[i] = 0.f; g_deg[i] = 0.f; }
    if (i < HC) { g_bnsum[i] = 0.f; g_bnsq[i] = 0.f; }
}

// edge_index is int32 (JAX x64 disabled: jnp.int64 request materializes int32)
__global__ void __launch_bounds__(256) k_selfloop(const int* __restrict__ ei,
                                                  const float* __restrict__ ew) {
    int e = blockIdx.x * 256 + threadIdx.x;
    if (e >= NE) return;
    int d = ei[NE + e];
    atomicAdd(&g_wsum[d], ew[e]);
    atomicAdd(&g_deg[d], 1.0f);
}

__global__ void __launch_bounds__(256) k_loopw() {
    int i = blockIdx.x * 256 + threadIdx.x;
    if (i < NN) g_loopw[i] = g_wsum[i] / fmaxf(g_deg[i], 1.0f);
}

// zero agg (NN*32 float4) + denom (NN float4) before each layer's edge phase
__global__ void __launch_bounds__(256) k_zero_edge() {
    int i = blockIdx.x * 256 + threadIdx.x;
    float4 z = make_float4(0.f, 0.f, 0.f, 0.f);
    if (i < NN * 32) g_agg[i] = z;
    if (i < NN)      g_denom[i] = z;
}

// ---------------- SGEMM: C[M,128] = A[M,128] @ W[128,128] + bias ------------
// asel: 0 -> external A, 1 -> g_h1 ; csel: 0 -> g_xl, 1 -> g_xr
__global__ void __launch_bounds__(256) k_sgemm(const float* __restrict__ Aext,
                                               int asel, int csel,
                                               const float* __restrict__ W,
                                               const float* __restrict__ bias,
                                               int M) {
    __shared__ float As[8][128];
    __shared__ float Bs[8][128];
    const float* A = asel ? (const float*)g_h1 : Aext;
    float*       C = csel ? (float*)g_xr : (float*)g_xl;

    const int tid = threadIdx.x;
    const int rowBase = blockIdx.x * 128;
    const int tm = (tid >> 4) << 3;
    const int tn = (tid & 15) << 3;

    float acc[8][8];
#pragma unroll
    for (int i = 0; i < 8; i++)
#pragma unroll
        for (int j = 0; j < 8; j++) acc[i][j] = 0.f;

    const int lm = tid >> 1;          // row within tile for A load
    const int lk = (tid & 1) << 2;    // 0 or 4
    const int bk = tid >> 5;          // 0..7
    const int bn = (tid & 31) << 2;   // 0..124

    int arow = rowBase + lm;
    if (arow >= M) arow = M - 1;      // clamp (stores are guarded)
    const float* Ab = A + arow * 128;

    for (int k0 = 0; k0 < 128; k0 += 8) {
        float4 a = *(const float4*)(Ab + k0 + lk);
        As[lk + 0][lm] = a.x; As[lk + 1][lm] = a.y;
        As[lk + 2][lm] = a.z; As[lk + 3][lm] = a.w;
        *(float4*)&Bs[bk][bn] = *(const float4*)(W + (k0 + bk) * 128 + bn);
        __syncthreads();
#pragma unroll
        for (int kk = 0; kk < 8; kk++) {
            float ra[8], rb[8];
            *(float4*)(ra)     = *(const float4*)&As[kk][tm];
            *(float4*)(ra + 4) = *(const float4*)&As[kk][tm + 4];
            *(float4*)(rb)     = *(const float4*)&Bs[kk][tn];
            *(float4*)(rb + 4) = *(const float4*)&Bs[kk][tn + 4];
#pragma unroll
            for (int i = 0; i < 8; i++)
#pragma unroll
                for (int j = 0; j < 8; j++)
                    acc[i][j] = fmaf(ra[i], rb[j], acc[i][j]);
        }
        __syncthreads();
    }
#pragma unroll
    for (int i = 0; i < 8; i++) {
        int r = rowBase + tm + i;
        if (r < M) {
#pragma unroll
            for (int j = 0; j < 8; j += 4) {
                float4 o;
                o.x = acc[i][j + 0] + bias[tn + j + 0];
                o.y = acc[i][j + 1] + bias[tn + j + 1];
                o.z = acc[i][j + 2] + bias[tn + j + 2];
                o.w = acc[i][j + 3] + bias[tn + j + 3];
                *(float4*)(C + r * 128 + tn + j) = o;
            }
        }
    }
}

// ---------------- edge pass 1: logits -> exp -> denom ------------------------
// one warp per edge; lane handles comps [4*lane, 4*lane+4); head = lane/8
__global__ void __launch_bounds__(256) k_edge1(const int* __restrict__ ei,
                                               const float* __restrict__ ew,
                                               const float* __restrict__ We,
                                               const float* __restrict__ att) {
    int gw = (blockIdx.x * 256 + threadIdx.x) >> 5;
    if (gw >= NE2) return;
    int lane = threadIdx.x & 31;
    int s, d; float w;
    if (gw < NE) {
        s = ei[gw]; d = ei[NE + gw]; w = ew[gw];
    } else {
        s = gw - NE; d = s; w = g_loopw[s];
    }
    float4 a  = g_xl[s * 32 + lane];
    float4 b  = g_xr[d * 32 + lane];
    float4 e4 = ((const float4*)We)[lane];
    float4 t4 = ((const float4*)att)[lane];

    float mx = fmaf(w, e4.x, a.x + b.x); mx = mx > 0.f ? mx : 0.2f * mx;
    float my = fmaf(w, e4.y, a.y + b.y); my = my > 0.f ? my : 0.2f * my;
    float mz = fmaf(w, e4.z, a.z + b.z); mz = mz > 0.f ? mz : 0.2f * mz;
    float mw = fmaf(w, e4.w, a.w + b.w); mw = mw > 0.f ? mw : 0.2f * mw;

    float p = mx * t4.x + my * t4.y + mz * t4.z + mw * t4.w;
    p += __shfl_xor_sync(0xffffffffu, p, 4);
    p += __shfl_xor_sync(0xffffffffu, p, 2);
    p += __shfl_xor_sync(0xffffffffu, p, 1);

    if ((lane & 7) == 0) {
        // logits are tiny (weights scaled by 0.05): exp without max-shift is
        // mathematically identical to the max-shifted softmax and fp32-safe
        float e = __expf(p);
        int h = lane >> 3;
        ((float*)g_ex)[gw * 4 + h] = e;
        atomicAdd(((float*)g_denom) + d * 4 + h, e);
    }
}

// ---------------- edge pass 2: scatter xl[src] * alpha into agg[dst] ---------
__global__ void __launch_bounds__(256) k_edge2(const int* __restrict__ ei) {
    int gw = (blockIdx.x * 256 + threadIdx.x) >> 5;
    if (gw >= NE2) return;
    int lane = threadIdx.x & 31;
    int s, d;
    if (gw < NE) { s = ei[gw]; d = ei[NE + gw]; }
    else         { s = gw - NE; d = s; }
    int h = lane >> 3;
    float alpha = ((const float*)g_ex)[gw * 4 + h] /
                  ((const float*)g_denom)[d * 4 + h];
    float4 v = g_xl[s * 32 + lane];
    float* dst = (float*)g_agg + d * 128 + lane * 4;
    atomicAdd(dst + 0, v.x * alpha);
    atomicAdd(dst + 1, v.y * alpha);
    atomicAdd(dst + 2, v.z * alpha);
    atomicAdd(dst + 3, v.w * alpha);
}

// ---------------- batchnorm ---------------------------------------------------
__global__ void __launch_bounds__(256) k_bnstats() {
    int t = threadIdx.x;
    int f4 = t & 31;
    float4 s = make_float4(0.f, 0.f, 0.f, 0.f);
    float4 q = make_float4(0.f, 0.f, 0.f, 0.f);
    for (int r = blockIdx.x * 8 + (t >> 5); r < NN; r += gridDim.x * 8) {
        float4 v = g_agg[r * 32 + f4];
        s.x += v.x; s.y += v.y; s.z += v.z; s.w += v.w;
        q.x += v.x * v.x; q.y += v.y * v.y; q.z += v.z * v.z; q.w += v.w * v.w;
    }
    int j = f4 * 4;
    atomicAdd(&g_bnsum[j + 0], s.x); atomicAdd(&g_bnsum[j + 1], s.y);
    atomicAdd(&g_bnsum[j + 2], s.z); atomicAdd(&g_bnsum[j + 3], s.w);
    atomicAdd(&g_bnsq[j + 0], q.x);  atomicAdd(&g_bnsq[j + 1], q.y);
    atomicAdd(&g_bnsq[j + 2], q.z);  atomicAdd(&g_bnsq[j + 3], q.w);
}

__global__ void __launch_bounds__(128) k_bnfin(const float* __restrict__ gamma,
                                               const float* __restrict__ beta) {
    int j = threadIdx.x;
    float mean = g_bnsum[j] * (1.0f / NN);
    float var  = g_bnsq[j] * (1.0f / NN) - mean * mean;
    float inv  = rsqrtf(var + 1e-5f);
    float sc   = gamma[j] * inv;
    ((float*)g_bnscale)[j] = sc;
    ((float*)g_bnshift)[j] = beta[j] - mean * sc;
}

__global__ void __launch_bounds__(256) k_bnapply() {
    int i = blockIdx.x * 256 + threadIdx.x;
    if (i >= NN * 32) return;
    int f4 = i & 31;
    float4 v  = g_agg[i];
    float4 sc = g_bnscale[f4];
    float4 sh = g_bnshift[f4];
    float x;
    x = fmaf(v.x, sc.x, sh.x); v.x = x > 0.f ? x : expm1f(x);
    x = fmaf(v.y, sc.y, sh.y); v.y = x > 0.f ? x : expm1f(x);
    x = fmaf(v.z, sc.z, sh.z); v.z = x > 0.f ? x : expm1f(x);
    x = fmaf(v.w, sc.w, sh.w); v.w = x > 0.f ? x : expm1f(x);
    g_h1[i] = v;
}

// ---------------- fusion ------------------------------------------------------
__global__ void __launch_bounds__(256) k_final(const float* __restrict__ emb,
                                               const float* __restrict__ bias2,
                                               float* __restrict__ out) {
    int i = blockIdx.x * 256 + threadIdx.x;
    if (i >= NN * 32) return;
    int f4 = i & 31;
    float4 e = ((const float4*)emb)[i];
    float4 h = g_h1[i];
    float4 g = g_agg[i];
    float4 b = ((const float4*)bias2)[f4];
    float4 o;
    const float third = 1.0f / 3.0f;
    o.x = (e.x + h.x + g.x + b.x) * third;
    o.y = (e.y + h.y + g.y + b.y) * third;
    o.z = (e.z + h.z + g.z + b.z) * third;
    o.w = (e.w + h.w + g.w + b.w) * third;
    ((float4*)out)[i] = o;
}

// ---------------- launch ------------------------------------------------------
extern "C" void kernel_launch(void* const* d_in, const int* in_sizes, int n_in,
                              void* d_out, int out_size) {
    const float* emb   = (const float*)d_in[0];
    const int*   ei    = (const int*)d_in[1];      // int32 (see note in k_selfloop)
    const float* ew    = (const float*)d_in[2];
    const float* Wl1   = (const float*)d_in[3];
    const float* bl1   = (const float*)d_in[4];
    const float* Wr1   = (const float*)d_in[5];
    const float* br1   = (const float*)d_in[6];
    const float* We1   = (const float*)d_in[7];
    const float* att1  = (const float*)d_in[8];
    // d_in[9]  = bias1 : cancels exactly inside BatchNorm, unused
    const float* gamma1 = (const float*)d_in[10];
    const float* beta1  = (const float*)d_in[11];
    const float* Wl2   = (const float*)d_in[12];
    const float* bl2   = (const float*)d_in[13];
    const float* Wr2   = (const float*)d_in[14];
    const float* br2   = (const float*)d_in[15];
    const float* We2   = (const float*)d_in[16];
    const float* att2  = (const float*)d_in[17];
    const float* bias2 = (const float*)d_in[18];
    float* out = (float*)d_out;

    const int NB_N = (NN + 255) / 256;
    const int NB_E = (NE + 255) / 256;
    const int NB_W = (NE2 * 32 + 255) / 256;   // warp-per-edge kernels
    const int NB_F = (NN * 32 + 255) / 256;    // float4-per-thread node kernels
    const int NB_G = (NN + 127) / 128;         // sgemm row tiles

    // self-loop attr (fill_value='mean')
    k_zero_pre<<<NB_N, 256>>>();
    k_selfloop<<<NB_E, 256>>>(ei, ew);
    k_loopw<<<NB_N, 256>>>();

    // ---- layer 1 ----
    k_sgemm<<<NB_G, 256>>>(emb, 0, 0, Wl1, bl1, NN);
    k_sgemm<<<NB_G, 256>>>(emb, 0, 1, Wr1, br1, NN);
    k_zero_edge<<<NB_F, 256>>>();
    k_edge1<<<NB_W, 256>>>(ei, ew, We1, att1);
    k_edge2<<<NB_W, 256>>>(ei);
    k_bnstats<<<512, 256>>>();
    k_bnfin<<<1, 128>>>(gamma1, beta1);
    k_bnapply<<<NB_F, 256>>>();

    // ---- layer 2 ----
    k_sgemm<<<NB_G, 256>>>(emb, 1, 0, Wl2, bl2, NN);
    k_sgemm<<<NB_G, 256>>>(emb, 1, 1, Wr2, br2, NN);
    k_zero_edge<<<NB_F, 256>>>();
    k_edge1<<<NB_W, 256>>>(ei, ew, We2, att2);
    k_edge2<<<NB_W, 256>>>(ei);

    // fusion: (emb + h1 + (agg + bias2)) / 3
    k_final<<<NB_F, 256>>>(emb, bias2, out);
}

// round 7
// speedup vs baseline: 2.0068x; 2.0068x over previous
#include <cuda_runtime.h>
#include <cuda_bf16.h>
#include <math.h>

#define NN    50000
#define NE    800000
#define NE2   850000           // NE + NN self loops
#define HC    128
#define NBLK  196              // ceil(NN/256)

// ---------------- scratch (device globals) ----------------------------------
__device__ float  g_wsum[NN];
__device__ float  g_deg[NN];
__device__ float  g_loopw[NN];
__device__ int    g_degc[NN];          // int degree incl self-loop
__device__ int    g_rowp[NN + 1];
__device__ int    g_fill[NN];
__device__ int    g_blksum[256];
__device__ int    g_blkoff[256];
__device__ int    g_csrc[NE2];         // CSR src per dst-bucket
__device__ float  g_cw[NE2];           // CSR edge weight
__device__ float4 g_xl[NN * 32];
__device__ float4 g_xr[NN * 32];
__device__ float4 g_agg[NN * 32];
__device__ float4 g_h1[NN * 32];
__device__ float  g_bnsum[HC];
__device__ float  g_bnsq[HC];
__device__ float4 g_bnscale[32];
__device__ float4 g_bnshift[32];

// ---------------- init ------------------------------------------------------
__global__ void __launch_bounds__(256) k_zero_pre() {
    int i = blockIdx.x * 256 + threadIdx.x;
    if (i < NN) { g_wsum[i] = 0.f; g_deg[i] = 0.f; g_degc[i] = 1; }
    if (i < HC) { g_bnsum[i] = 0.f; g_bnsq[i] = 0.f; }
}

// edge_index is int32 (JAX default x64-disabled)
__global__ void __launch_bounds__(256) k_selfloop(const int* __restrict__ ei,
                                                  const float* __restrict__ ew) {
    int e = blockIdx.x * 256 + threadIdx.x;
    if (e >= NE) return;
    int d = ei[NE + e];
    atomicAdd(&g_wsum[d], ew[e]);
    atomicAdd(&g_deg[d], 1.0f);
    atomicAdd(&g_degc[d], 1);
}

__global__ void __launch_bounds__(256) k_loopw() {
    int i = blockIdx.x * 256 + threadIdx.x;
    if (i < NN) g_loopw[i] = g_wsum[i] / fmaxf(g_deg[i], 1.0f);
}

// ---------------- exclusive scan of g_degc -> g_rowp ------------------------
__global__ void __launch_bounds__(256) k_scan1() {
    __shared__ int sm[256];
    int t = threadIdx.x;
    int i = blockIdx.x * 256 + t;
    int v = (i < NN) ? g_degc[i] : 0;
    sm[t] = v;
    __syncthreads();
#pragma unroll
    for (int off = 1; off < 256; off <<= 1) {
        int x = (t >= off) ? sm[t - off] : 0;
        __syncthreads();
        sm[t] += x;
        __syncthreads();
    }
    if (i < NN) g_rowp[i] = sm[t] - v;      // exclusive within block
    if (t == 255) g_blksum[blockIdx.x] = sm[t];
}

__global__ void __launch_bounds__(256) k_scan2() {
    __shared__ int sm[256];
    int t = threadIdx.x;
    int v = (t < NBLK) ? g_blksum[t] : 0;
    sm[t] = v;
    __syncthreads();
#pragma unroll
    for (int off = 1; off < 256; off <<= 1) {
        int x = (t >= off) ? sm[t - off] : 0;
        __syncthreads();
        sm[t] += x;
        __syncthreads();
    }
    g_blkoff[t] = sm[t] - v;                // exclusive block offset
}

__global__ void __launch_bounds__(256) k_scan3() {
    int i = blockIdx.x * 256 + threadIdx.x;
    if (i < NN) {
        int r = g_rowp[i] + g_blkoff[blockIdx.x];
        g_rowp[i] = r;
        g_fill[i] = r;
    }
    if (i == 0) g_rowp[NN] = NE2;
}

// ---------------- CSR fill (grouped by dst; order within bucket free) -------
__global__ void __launch_bounds__(256) k_fill(const int* __restrict__ ei,
                                              const float* __restrict__ ew) {
    int e = blockIdx.x * 256 + threadIdx.x;
    if (e >= NE2) return;
    if (e < NE) {
        int s = ei[e], d = ei[NE + e];
        int pos = atomicAdd(&g_fill[d], 1);
        g_csrc[pos] = s;
        g_cw[pos] = ew[e];
    } else {
        int i = e - NE;
        int pos = atomicAdd(&g_fill[i], 1);
        g_csrc[pos] = i;
        g_cw[pos] = g_loopw[i];
    }
}

// ---------------- SGEMM: C[M,128] = A[M,128] @ W[128,128] + bias ------------
// blockIdx.y selects (W0,b0)->g_xl vs (W1,b1)->g_xr ; asel: 0 ext A, 1 g_h1
__global__ void __launch_bounds__(256) k_sgemm(const float* __restrict__ Aext,
                                               int asel,
                                               const float* __restrict__ W0,
                                               const float* __restrict__ b0,
                                               const float* __restrict__ W1,
                                               const float* __restrict__ b1,
                                               int M) {
    __shared__ float As[8][128];
    __shared__ float Bs[8][128];
    const float* A    = asel ? (const float*)g_h1 : Aext;
    const float* W    = blockIdx.y ? W1 : W0;
    const float* bias = blockIdx.y ? b1 : b0;
    float*       C    = blockIdx.y ? (float*)g_xr : (float*)g_xl;

    const int tid = threadIdx.x;
    const int rowBase = blockIdx.x * 128;
    const int tm = (tid >> 4) << 3;
    const int tn = (tid & 15) << 3;

    float acc[8][8];
#pragma unroll
    for (int i = 0; i < 8; i++)
#pragma unroll
        for (int j = 0; j < 8; j++) acc[i][j] = 0.f;

    const int lm = tid >> 1;
    const int lk = (tid & 1) << 2;
    const int bk = tid >> 5;
    const int bn = (tid & 31) << 2;

    int arow = rowBase + lm;
    if (arow >= M) arow = M - 1;
    const float* Ab = A + arow * 128;

    for (int k0 = 0; k0 < 128; k0 += 8) {
        float4 a = *(const float4*)(Ab + k0 + lk);
        As[lk + 0][lm] = a.x; As[lk + 1][lm] = a.y;
        As[lk + 2][lm] = a.z; As[lk + 3][lm] = a.w;
        *(float4*)&Bs[bk][bn] = *(const float4*)(W + (k0 + bk) * 128 + bn);
        __syncthreads();
#pragma unroll
        for (int kk = 0; kk < 8; kk++) {
            float ra[8], rb[8];
            *(float4*)(ra)     = *(const float4*)&As[kk][tm];
            *(float4*)(ra + 4) = *(const float4*)&As[kk][tm + 4];
            *(float4*)(rb)     = *(const float4*)&Bs[kk][tn];
            *(float4*)(rb + 4) = *(const float4*)&Bs[kk][tn + 4];
#pragma unroll
            for (int i = 0; i < 8; i++)
#pragma unroll
                for (int j = 0; j < 8; j++)
                    acc[i][j] = fmaf(ra[i], rb[j], acc[i][j]);
        }
        __syncthreads();
    }
#pragma unroll
    for (int i = 0; i < 8; i++) {
        int r = rowBase + tm + i;
        if (r < M) {
#pragma unroll
            for (int j = 0; j < 8; j += 4) {
                float4 o;
                o.x = acc[i][j + 0] + bias[tn + j + 0];
                o.y = acc[i][j + 1] + bias[tn + j + 1];
                o.z = acc[i][j + 2] + bias[tn + j + 2];
                o.w = acc[i][j + 3] + bias[tn + j + 3];
                *(float4*)(C + r * 128 + tn + j) = o;
            }
        }
    }
}

// ---------------- fused GATv2 attention: one warp per dst node --------------
// out[d] = sum_e exp(l_e) * xl[src_e] / sum_e exp(l_e)
// lane handles comps [4*lane,4*lane+4); head = lane>>3 (C_OUT=32 = 8 lanes)
__global__ void __launch_bounds__(256) k_gat(const float* __restrict__ We,
                                             const float* __restrict__ att) {
    int node = (blockIdx.x * 256 + threadIdx.x) >> 5;
    if (node >= NN) return;
    int lane = threadIdx.x & 31;

    float4 b  = g_xr[node * 32 + lane];
    float4 e4 = ((const float4*)We)[lane];
    float4 t4 = ((const float4*)att)[lane];

    int beg = g_rowp[node];
    int end = g_rowp[node + 1];

    float4 acc = make_float4(0.f, 0.f, 0.f, 0.f);
    float denom = 0.f;

    // software pipeline: prefetch next (src, w) and next xl row
    int   s = g_csrc[beg];
    float w = g_cw[beg];
    float4 a = g_xl[s * 32 + lane];

    for (int j = beg; j < end; j++) {
        int jn = (j + 1 < end) ? j + 1 : j;
        int   sn = g_csrc[jn];
        float wn = g_cw[jn];
        float4 an = g_xl[sn * 32 + lane];

        // leakyrelu(x) = max(x, 0.2x) since slope < 1
        float mx = fmaf(w, e4.x, a.x + b.x); mx = fmaxf(mx, 0.2f * mx);
        float my = fmaf(w, e4.y, a.y + b.y); my = fmaxf(my, 0.2f * my);
        float mz = fmaf(w, e4.z, a.z + b.z); mz = fmaxf(mz, 0.2f * mz);
        float mw = fmaf(w, e4.w, a.w + b.w); mw = fmaxf(mw, 0.2f * mw);

        float p = mx * t4.x + my * t4.y + mz * t4.z + mw * t4.w;
        p += __shfl_xor_sync(0xffffffffu, p, 4);
        p += __shfl_xor_sync(0xffffffffu, p, 2);
        p += __shfl_xor_sync(0xffffffffu, p, 1);
        // p is now the per-head logit (same across the 8 lanes of this head).
        // logits are tiny (weights scaled 0.05): exp without max-shift is
        // mathematically identical to the shifted softmax and fp32-safe.
        float e = __expf(p);
        denom += e;
        acc.x = fmaf(e, a.x, acc.x);
        acc.y = fmaf(e, a.y, acc.y);
        acc.z = fmaf(e, a.z, acc.z);
        acc.w = fmaf(e, a.w, acc.w);

        a = an; w = wn;
    }

    float inv = __frcp_rn(denom);   // denom >= exp(self-loop) > 0
    acc.x *= inv; acc.y *= inv; acc.z *= inv; acc.w *= inv;
    g_agg[node * 32 + lane] = acc;
}

// ---------------- batchnorm -------------------------------------------------
__global__ void __launch_bounds__(256) k_bnstats() {
    int t = threadIdx.x;
    int f4 = t & 31;
    float4 s = make_float4(0.f, 0.f, 0.f, 0.f);
    float4 q = make_float4(0.f, 0.f, 0.f, 0.f);
    for (int r = blockIdx.x * 8 + (t >> 5); r < NN; r += gridDim.x * 8) {
        float4 v = g_agg[r * 32 + f4];
        s.x += v.x; s.y += v.y; s.z += v.z; s.w += v.w;
        q.x += v.x * v.x; q.y += v.y * v.y; q.z += v.z * v.z; q.w += v.w * v.w;
    }
    int j = f4 * 4;
    atomicAdd(&g_bnsum[j + 0], s.x); atomicAdd(&g_bnsum[j + 1], s.y);
    atomicAdd(&g_bnsum[j + 2], s.z); atomicAdd(&g_bnsum[j + 3], s.w);
    atomicAdd(&g_bnsq[j + 0], q.x);  atomicAdd(&g_bnsq[j + 1], q.y);
    atomicAdd(&g_bnsq[j + 2], q.z);  atomicAdd(&g_bnsq[j + 3], q.w);
}

__global__ void __launch_bounds__(128) k_bnfin(const float* __restrict__ gamma,
                                               const float* __restrict__ beta) {
    int j = threadIdx.x;
    float mean = g_bnsum[j] * (1.0f / NN);
    float var  = g_bnsq[j] * (1.0f / NN) - mean * mean;
    float inv  = rsqrtf(var + 1e-5f);
    float sc   = gamma[j] * inv;
    ((float*)g_bnscale)[j] = sc;
    ((float*)g_bnshift)[j] = beta[j] - mean * sc;
}

__global__ void __launch_bounds__(256) k_bnapply() {
    int i = blockIdx.x * 256 + threadIdx.x;
    if (i >= NN * 32) return;
    int f4 = i & 31;
    float4 v  = g_agg[i];
    float4 sc = g_bnscale[f4];
    float4 sh = g_bnshift[f4];
    float x;
    x = fmaf(v.x, sc.x, sh.x); v.x = x > 0.f ? x : expm1f(x);
    x = fmaf(v.y, sc.y, sh.y); v.y = x > 0.f ? x : expm1f(x);
    x = fmaf(v.z, sc.z, sh.z); v.z = x > 0.f ? x : expm1f(x);
    x = fmaf(v.w, sc.w, sh.w); v.w = x > 0.f ? x : expm1f(x);
    g_h1[i] = v;
}

// ---------------- fusion ----------------------------------------------------
__global__ void __launch_bounds__(256) k_final(const float* __restrict__ emb,
                                               const float* __restrict__ bias2,
                                               float* __restrict__ out) {
    int i = blockIdx.x * 256 + threadIdx.x;
    if (i >= NN * 32) return;
    int f4 = i & 31;
    float4 e = ((const float4*)emb)[i];
    float4 h = g_h1[i];
    float4 g = g_agg[i];
    float4 bb = ((const float4*)bias2)[f4];
    float4 o;
    const float third = 1.0f / 3.0f;
    o.x = (e.x + h.x + g.x + bb.x) * third;
    o.y = (e.y + h.y + g.y + bb.y) * third;
    o.z = (e.z + h.z + g.z + bb.z) * third;
    o.w = (e.w + h.w + g.w + bb.w) * third;
    ((float4*)out)[i] = o;
}

// ---------------- launch ----------------------------------------------------
extern "C" void kernel_launch(void* const* d_in, const int* in_sizes, int n_in,
                              void* d_out, int out_size) {
    const float* emb   = (const float*)d_in[0];
    const int*   ei    = (const int*)d_in[1];      // int32
    const float* ew    = (const float*)d_in[2];
    const float* Wl1   = (const float*)d_in[3];
    const float* bl1   = (const float*)d_in[4];
    const float* Wr1   = (const float*)d_in[5];
    const float* br1   = (const float*)d_in[6];
    const float* We1   = (const float*)d_in[7];
    const float* att1  = (const float*)d_in[8];
    // d_in[9] = bias1 : cancels exactly inside BatchNorm, unused
    const float* gamma1 = (const float*)d_in[10];
    const float* beta1  = (const float*)d_in[11];
    const float* Wl2   = (const float*)d_in[12];
    const float* bl2   = (const float*)d_in[13];
    const float* Wr2   = (const float*)d_in[14];
    const float* br2   = (const float*)d_in[15];
    const float* We2   = (const float*)d_in[16];
    const float* att2  = (const float*)d_in[17];
    const float* bias2 = (const float*)d_in[18];
    float* out = (float*)d_out;

    const int NB_N  = NBLK;                     // node-count blocks
    const int NB_E  = (NE + 255) / 256;
    const int NB_E2 = (NE2 + 255) / 256;
    const int NB_W  = (NN * 32 + 255) / 256;    // warp-per-node kernels
    const int NB_F  = (NN * 32 + 255) / 256;    // float4-per-thread kernels
    dim3 gemm_grid((NN + 127) / 128, 2);

    // ---- preprocessing: self-loop attrs + CSR (grouped by dst) ----
    k_zero_pre<<<NB_N, 256>>>();
    k_selfloop<<<NB_E, 256>>>(ei, ew);
    k_loopw<<<NB_N, 256>>>();
    k_scan1<<<NBLK, 256>>>();
    k_scan2<<<1, 256>>>();
    k_scan3<<<NBLK, 256>>>();
    k_fill<<<NB_E2, 256>>>(ei, ew);

    // ---- layer 1 ----
    k_sgemm<<<gemm_grid, 256>>>(emb, 0, Wl1, bl1, Wr1, br1, NN);
    k_gat<<<NB_W, 256>>>(We1, att1);
    k_bnstats<<<512, 256>>>();
    k_bnfin<<<1, 128>>>(gamma1, beta1);
    k_bnapply<<<NB_F, 256>>>();

    // ---- layer 2 ----
    k_sgemm<<<gemm_grid, 256>>>(emb, 1, Wl2, bl2, Wr2, br2, NN);
    k_gat<<<NB_W, 256>>>(We2, att2);

    // fusion: (emb + h1 + (agg + bias2)) / 3
    k_final<<<NB_F, 256>>>(emb, bias2, out);
}